// round 2
// baseline (speedup 1.0000x reference)
#include <cuda_runtime.h>
#include <math.h>

#define NSTEPS 130
#define NLUT   27
#define ROWS   32                     // padded lanes per step row in SMEM
#define NITER  (NSTEPS / 2)           // 65 fused 2-step iterations

// srcA[l] / srcB[l]: the flat-state index whose value feeds mux selects A / B
// of LUT-lane l. Derived from IDX0/1/2 with the per-j select folded in:
//   srcA = (j==0) ? IDX1[t] : IDX0[t];  srcB = (j==2) ? IDX1[t] : IDX2[t]
// Lanes 27..31 are constant-carrier lanes (self-wired).
__device__ __constant__ int c_srcA[32] = {
    1, 3, 3,   7, 0, 0,   4, 6, 6,   19, 12, 12,  16, 9, 9,
    13, 15, 15, 10, 18, 18, 22, 6, 6, 25, 15, 15,
    27, 28, 29, 30, 31};
__device__ __constant__ int c_srcB[32] = {
    17, 17, 1,  5, 5, 7,   11, 11, 4, 8, 8, 19,   28, 28, 16,
    2, 2, 13,   27, 27, 10, 23, 23, 22, 26, 26, 25,
    27, 28, 29, 30, 31};

__global__ void one_layer_net_kernel(const float* __restrict__ x,
                                     const float* __restrict__ weights,
                                     const float4* __restrict__ noise4,
                                     float* __restrict__ out) {
    // s_uvrs[s][l] = (u,v,r,s) such that new_state = B*(A*u+v) + (A*r+s)
    extern __shared__ float4 s_uvrs[];   // [130][32] float4 = 66560 B

    const int tid  = threadIdx.x;
    const int wrp  = tid >> 5;
    const int lane = tid & 31;

    // ---------------- Phase 1: parallel precompute of (u,v,r,s) ------------
    {
        const bool act = (lane < NLUT);
        float4 wb = make_float4(0.f, 0.f, 0.f, 0.f);
        if (act) wb = reinterpret_cast<const float4*>(weights)[lane];
        // step-invariant noise gain |1-|w||*0.125
        const float c0 = fabsf(1.0f - fabsf(wb.x)) * 0.125f;
        const float c1 = fabsf(1.0f - fabsf(wb.y)) * 0.125f;
        const float c2 = fabsf(1.0f - fabsf(wb.z)) * 0.125f;
        const float c3 = fabsf(1.0f - fabsf(wb.w)) * 0.125f;
        const float xv = (lane == 27) ? x[0] : ((lane == 28) ? x[1] : 0.0f);
        const int   nl = act ? lane : 0;

        for (int s = wrp; s < NSTEPS; s += 8) {
            const float4 n = noise4[s * NLUT + nl];
            const float w0 = fmaf(c0, n.x, wb.x);
            const float w1 = fmaf(c1, n.y, wb.y);
            const float w2 = fmaf(c2, n.z, wb.z);
            const float w3 = fmaf(c3, n.w, wb.w);
            const float d01 = w1 - w0, d23 = w3 - w2;
            const float p01 = w0 + w1, p23 = w2 + w3;
            float4 q;
            q.x = 0.25f * (d23 - d01);   // u
            q.y = 0.25f * (p23 - p01);   // v
            q.z = 0.25f * (d01 + d23);   // r
            q.w = 0.25f * (p01 + p23);   // s
            if (!act) { q.x = 0.f; q.y = 0.f; q.z = 0.f; q.w = xv; }
            s_uvrs[s * ROWS + lane] = q;
        }
    }
    __syncthreads();

    if (tid >= 32) return;   // warp 0 runs the serial scan

    // ---------------- Phase 2: fused 2-step serial scan --------------------
    // Composite wiring: to produce state_{s+2}(l) we locally evaluate the two
    // source LUTs sa=srcA(l), sb=srcB(l) at step s (their selects come from
    // grandparent lanes via 4 parallel shfls), then our own LUT at step s+1.
    const int sa = c_srcA[lane];
    const int sb = c_srcB[lane];
    const int aa = c_srcA[sa], ba = c_srcB[sa];
    const int ab = c_srcA[sb], bb = c_srcB[sb];

    float state = (lane < NLUT) ? -1.0f
                : (lane == 27) ? x[0]
                : (lane == 28) ? x[1] : 0.0f;

    // Prefetch ring (depth 1): quadruples for iteration k held in cA/cB/cF.
    float4 cA = s_uvrs[0 * ROWS + sa];
    float4 cB = s_uvrs[0 * ROWS + sb];
    float4 cF = s_uvrs[1 * ROWS + lane];

#pragma unroll 5
    for (int k = 0; k < NITER; ++k) {
        // Prefetch next iteration's quadruples (off the critical path).
        const int kk = (k + 1 < NITER) ? (k + 1) : k;
        const float4 pA = s_uvrs[(2 * kk) * ROWS + sa];
        const float4 pB = s_uvrs[(2 * kk) * ROWS + sb];
        const float4 pF = s_uvrs[(2 * kk + 1) * ROWS + lane];

        // Grandparent states (all depend only on `state` -> 4 parallel shfls).
        const float aAv = __shfl_sync(0xFFFFFFFFu, state, aa);
        const float bAv = __shfl_sync(0xFFFFFFFFu, state, ba);
        const float aBv = __shfl_sync(0xFFFFFFFFu, state, ab);
        const float bBv = __shfl_sync(0xFFFFFFFFu, state, bb);

        // Intermediate states of our two source LUTs (step 2k).
        const float iA = fmaf(bAv, fmaf(aAv, cA.x, cA.y), fmaf(aAv, cA.z, cA.w));
        const float iB = fmaf(bBv, fmaf(aBv, cB.x, cB.y), fmaf(aBv, cB.z, cB.w));

        // Our LUT at step 2k+1.
        state = fmaf(iB, fmaf(iA, cF.x, cF.y), fmaf(iA, cF.z, cF.w));

        cA = pA; cB = pB; cF = pF;
    }

    // Outputs: final[0,1] -> flat 1, final[1,2] -> flat 5, final[7,2] -> flat 23.
    if (lane == 1)  out[0] = state;
    if (lane == 5)  out[1] = state;
    if (lane == 23) out[2] = state;
}

extern "C" void kernel_launch(void* const* d_in, const int* in_sizes, int n_in,
                              void* d_out, int out_size) {
    (void)in_sizes; (void)n_in; (void)out_size;
    const float*  x  = (const float*)d_in[0];      // [2]
    const float*  w  = (const float*)d_in[1];      // [9,3,4]
    const float4* nz = (const float4*)d_in[2];     // [130,9,3,4] as float4
    float* out = (float*)d_out;                    // [3]

    const size_t smem = (size_t)NSTEPS * ROWS * sizeof(float4);   // 66560 B
    cudaFuncSetAttribute(one_layer_net_kernel,
                         cudaFuncAttributeMaxDynamicSharedMemorySize, (int)smem);
    one_layer_net_kernel<<<1, 256, smem>>>(x, w, nz, out);
}

// round 4
// speedup vs baseline: 1.1662x; 1.1662x over previous
#include <cuda_runtime.h>
#include <math.h>

#define NSTEPS 130
#define NLUT   27
#define ROWS   32                     // padded lanes per step row in uvrs SMEM
#define UROWS  (NSTEPS + 2)           // +2 padding rows: tail prefetch over-read lands here
#define NVEC   (NSTEPS * NLUT)        // 3510 raw noise float4s
#define NITER  (NSTEPS / 2)           // 65 fused 2-step iterations

// srcA[l] / srcB[l]: flat-state index feeding mux selects A / B of LUT-lane l.
//   srcA = (j==0) ? IDX1[t] : IDX0[t];  srcB = (j==2) ? IDX1[t] : IDX2[t]
// Lanes 27..31 are constant-carrier lanes (self-wired).
__device__ __constant__ int c_srcA[32] = {
    1, 3, 3,   7, 0, 0,   4, 6, 6,   19, 12, 12,  16, 9, 9,
    13, 15, 15, 10, 18, 18, 22, 6, 6, 25, 15, 15,
    27, 28, 29, 30, 31};
__device__ __constant__ int c_srcB[32] = {
    17, 17, 1,  5, 5, 7,   11, 11, 4, 8, 8, 19,   28, 28, 16,
    2, 2, 13,   27, 27, 10, 23, 23, 22, 26, 26, 25,
    27, 28, 29, 30, 31};

__global__ void one_layer_net_kernel(const float* __restrict__ x,
                                     const float* __restrict__ weights,
                                     const float4* __restrict__ noise4,
                                     float* __restrict__ out) {
    // Layout: [0, NVEC) raw noise, then [UROWS][32] uvrs quadruples.
    extern __shared__ float4 smem[];
    float4* s_raw  = smem;           // [3510]
    float4* s_uvrs = smem + NVEC;    // [132][32]; row s holds coeffs for step s

    const int tid  = threadIdx.x;
    const int wrp  = tid >> 5;
    const int lane = tid & 31;

    // ---- Phase 1a: coalesced raw copy, high MLP (independent LDG.128) -----
#pragma unroll
    for (int i = tid; i < NVEC; i += 256)
        s_raw[i] = noise4[i];
    __syncthreads();

    // ---- Phase 1b: compute (u,v,r,s) from SMEM ----------------------------
    // new_state = B*(A*u + v) + (A*r + s)
    {
        const bool act = (lane < NLUT);
        float4 wb = make_float4(0.f, 0.f, 0.f, 0.f);
        if (act) wb = reinterpret_cast<const float4*>(weights)[lane];
        const float c0 = fabsf(1.0f - fabsf(wb.x)) * 0.125f;
        const float c1 = fabsf(1.0f - fabsf(wb.y)) * 0.125f;
        const float c2 = fabsf(1.0f - fabsf(wb.z)) * 0.125f;
        const float c3 = fabsf(1.0f - fabsf(wb.w)) * 0.125f;
        const float xv = (lane == 27) ? x[0] : ((lane == 28) ? x[1] : 0.0f);
        const int   nl = act ? lane : 0;

#pragma unroll
        for (int s = wrp; s < NSTEPS; s += 8) {
            const float4 n = s_raw[s * NLUT + nl];
            const float w0 = fmaf(c0, n.x, wb.x);
            const float w1 = fmaf(c1, n.y, wb.y);
            const float w2 = fmaf(c2, n.z, wb.z);
            const float w3 = fmaf(c3, n.w, wb.w);
            const float d01 = w1 - w0, d23 = w3 - w2;
            const float p01 = w0 + w1, p23 = w2 + w3;
            float4 q;
            q.x = 0.25f * (d23 - d01);   // u
            q.y = 0.25f * (p23 - p01);   // v
            q.z = 0.25f * (d01 + d23);   // r
            q.w = 0.25f * (p01 + p23);   // s
            if (!act) { q.x = 0.f; q.y = 0.f; q.z = 0.f; q.w = xv; }
            s_uvrs[s * ROWS + lane] = q;
        }
        // Zero the 2 padding rows (warps 2,3 cover rows 130,131).
        if (wrp >= 2 && wrp < 4)
            s_uvrs[(NSTEPS + (wrp - 2)) * ROWS + lane] =
                make_float4(0.f, 0.f, 0.f, 0.f);
    }
    __syncthreads();

    if (tid >= 32) return;   // warp 0 runs the serial scan

    // ---- Phase 2: fused 2-step serial scan --------------------------------
    const int sa = c_srcA[lane];
    const int sb = c_srcB[lane];
    const int aa = c_srcA[sa], ba = c_srcB[sa];
    const int ab = c_srcA[sb], bb = c_srcB[sb];

    float state = (lane < NLUT) ? -1.0f
                : (lane == 27) ? x[0]
                : (lane == 28) ? x[1] : 0.0f;

    // Pointer-increment addressing: no per-iter IMADs on the index path.
    const float4* pAp = s_uvrs + sa;            // row 2k
    const float4* pBp = s_uvrs + sb;            // row 2k
    const float4* pFp = s_uvrs + ROWS + lane;   // row 2k+1

    float4 cA = pAp[0];
    float4 cB = pBp[0];
    float4 cF = pFp[0];
    pAp += 2 * ROWS; pBp += 2 * ROWS; pFp += 2 * ROWS;

#pragma unroll 5
    for (int k = 0; k < NITER; ++k) {
        // Prefetch next iteration's quadruples (tail reads land in padding rows).
        const float4 pA = pAp[0];
        const float4 pB = pBp[0];
        const float4 pF = pFp[0];
        pAp += 2 * ROWS; pBp += 2 * ROWS; pFp += 2 * ROWS;

        // Grandparent states: 4 parallel shfls off the single live register.
        const float aAv = __shfl_sync(0xFFFFFFFFu, state, aa);
        const float bAv = __shfl_sync(0xFFFFFFFFu, state, ba);
        const float aBv = __shfl_sync(0xFFFFFFFFu, state, ab);
        const float bBv = __shfl_sync(0xFFFFFFFFu, state, bb);

        // Two source LUTs at step 2k, then our LUT at step 2k+1.
        const float iA = fmaf(bAv, fmaf(aAv, cA.x, cA.y), fmaf(aAv, cA.z, cA.w));
        const float iB = fmaf(bBv, fmaf(aBv, cB.x, cB.y), fmaf(aBv, cB.z, cB.w));
        state = fmaf(iB, fmaf(iA, cF.x, cF.y), fmaf(iA, cF.z, cF.w));

        cA = pA; cB = pB; cF = pF;
    }

    // Outputs: final[0,1] -> flat 1, final[1,2] -> flat 5, final[7,2] -> flat 23.
    if (lane == 1)  out[0] = state;
    if (lane == 5)  out[1] = state;
    if (lane == 23) out[2] = state;
}

extern "C" void kernel_launch(void* const* d_in, const int* in_sizes, int n_in,
                              void* d_out, int out_size) {
    (void)in_sizes; (void)n_in; (void)out_size;
    const float*  x  = (const float*)d_in[0];      // [2]
    const float*  w  = (const float*)d_in[1];      // [9,3,4]
    const float4* nz = (const float4*)d_in[2];     // [130,9,3,4] as float4
    float* out = (float*)d_out;                    // [3]

    const size_t smem = (size_t)(NVEC + UROWS * ROWS) * sizeof(float4); // 123744 B
    cudaFuncSetAttribute(one_layer_net_kernel,
                         cudaFuncAttributeMaxDynamicSharedMemorySize, (int)smem);
    one_layer_net_kernel<<<1, 256, smem>>>(x, w, nz, out);
}

// round 5
// speedup vs baseline: 1.1905x; 1.0208x over previous
#include <cuda_runtime.h>
#include <math.h>

#define NSTEPS 130
#define NLUT   27
#define ROWS   32
#define UROWS  132          // 130 data rows + 2 padding rows for tail prefetch

// srcA[l] / srcB[l]: flat-state index feeding mux selects A / B of LUT-lane l.
// Lanes 27..31 are constant-carrier lanes (self-wired).
__device__ __constant__ int c_srcA[32] = {
    1, 3, 3,   7, 0, 0,   4, 6, 6,   19, 12, 12,  16, 9, 9,
    13, 15, 15, 10, 18, 18, 22, 6, 6, 25, 15, 15,
    27, 28, 29, 30, 31};
__device__ __constant__ int c_srcB[32] = {
    17, 17, 1,  5, 5, 7,   11, 11, 4, 8, 8, 19,   28, 28, 16,
    2, 2, 13,   27, 27, 10, 23, 23, 22, 26, 26, 25,
    27, 28, 29, 30, 31};

// Named-barrier producer/consumer handshake (64 = producer warp + consumer warp).
#define BAR_ARRIVE(b) asm volatile("bar.arrive %0, 64;" :: "r"(b) : "memory")
#define BAR_WAIT(b)   asm volatile("bar.sync %0, 64;"   :: "r"(b) : "memory")

__global__ void one_layer_net_kernel(const float* __restrict__ x,
                                     const float* __restrict__ weights,
                                     const float4* __restrict__ noise4,
                                     float* __restrict__ out) {
    extern __shared__ float4 s_uvrs[];   // [132][32] quadruples

    const int tid  = threadIdx.x;
    const int wrp  = tid >> 5;
    const int lane = tid & 31;

    if (wrp > 0) {
        // ------------------- PRODUCER WARPS (1..7) -------------------------
        const bool act = (lane < NLUT);
        const int  nl  = act ? lane : 0;
        float4 wb = make_float4(0.f, 0.f, 0.f, 0.f);
        if (act) wb = reinterpret_cast<const float4*>(weights)[lane];
        const float c0 = fabsf(1.0f - fabsf(wb.x)) * 0.125f;
        const float c1 = fabsf(1.0f - fabsf(wb.y)) * 0.125f;
        const float c2 = fabsf(1.0f - fabsf(wb.z)) * 0.125f;
        const float c3 = fabsf(1.0f - fabsf(wb.w)) * 0.125f;
        const float xv = (lane == 27) ? x[0] : ((lane == 28) ? x[1] : 0.0f);

        // Block map: warp1 -> rows 0..7 (small first block so the scan starts
        // early), warps 2..7 -> 20 rows each covering 8..127. Warp1 then does
        // rows 128..131 (incl. 2 zero padding rows) and arrives barrier 8.
        const int s0 = (wrp == 1) ? 0 : 8 + 20 * (wrp - 2);
        const int s1 = (wrp == 1) ? 8 : s0 + 20;

#pragma unroll 4
        for (int s = s0; s < s1; ++s) {
            const float4 n = noise4[s * NLUT + nl];
            const float w0 = fmaf(c0, n.x, wb.x);
            const float w1 = fmaf(c1, n.y, wb.y);
            const float w2 = fmaf(c2, n.z, wb.z);
            const float w3 = fmaf(c3, n.w, wb.w);
            const float d01 = w1 - w0, d23 = w3 - w2;
            const float p01 = w0 + w1, p23 = w2 + w3;
            float4 q;
            q.x = act ? 0.25f * (d23 - d01) : 0.f;
            q.y = act ? 0.25f * (p23 - p01) : 0.f;
            q.z = act ? 0.25f * (d01 + d23) : 0.f;
            q.w = act ? 0.25f * (p01 + p23) : xv;
            s_uvrs[s * ROWS + lane] = q;
        }
        BAR_ARRIVE(wrp);

        if (wrp == 1) {
            // rows 128,129 real; rows 130,131 padding (zero).
#pragma unroll
            for (int s = 128; s < 132; ++s) {
                float4 q = make_float4(0.f, 0.f, 0.f, 0.f);
                if (s < NSTEPS) {
                    const float4 n = noise4[s * NLUT + nl];
                    const float w0 = fmaf(c0, n.x, wb.x);
                    const float w1 = fmaf(c1, n.y, wb.y);
                    const float w2 = fmaf(c2, n.z, wb.z);
                    const float w3 = fmaf(c3, n.w, wb.w);
                    const float d01 = w1 - w0, d23 = w3 - w2;
                    const float p01 = w0 + w1, p23 = w2 + w3;
                    q.x = act ? 0.25f * (d23 - d01) : 0.f;
                    q.y = act ? 0.25f * (p23 - p01) : 0.f;
                    q.z = act ? 0.25f * (d01 + d23) : 0.f;
                    q.w = act ? 0.25f * (p01 + p23) : xv;
                }
                s_uvrs[s * ROWS + lane] = q;
            }
            int b8 = 8;
            BAR_ARRIVE(b8);
        }
        return;
    }

    // ----------------------- CONSUMER WARP (0) -----------------------------
    const int sa = c_srcA[lane];
    const int sb = c_srcB[lane];
    const int aa = c_srcA[sa], ba = c_srcB[sa];
    const int ab = c_srcA[sb], bb = c_srcB[sb];

    float state = (lane < NLUT) ? -1.0f
                : (lane == 27) ? x[0]
                : (lane == 28) ? x[1] : 0.0f;

    int b = 1;
    BAR_WAIT(b);   // rows 0..7 ready

    const float4* pAp = s_uvrs + sa;
    const float4* pBp = s_uvrs + sb;
    const float4* pFp = s_uvrs + ROWS + lane;
    float4 cA = pAp[0];
    float4 cB = pBp[0];
    float4 cF = pFp[0];
    pAp += 2 * ROWS; pBp += 2 * ROWS; pFp += 2 * ROWS;

#define SCAN_ITER()                                                          \
    do {                                                                     \
        const float4 pA = pAp[0];                                            \
        const float4 pB = pBp[0];                                            \
        const float4 pF = pFp[0];                                            \
        pAp += 2 * ROWS; pBp += 2 * ROWS; pFp += 2 * ROWS;                   \
        const float aAv = __shfl_sync(0xFFFFFFFFu, state, aa);               \
        const float bAv = __shfl_sync(0xFFFFFFFFu, state, ba);               \
        const float aBv = __shfl_sync(0xFFFFFFFFu, state, ab);               \
        const float bBv = __shfl_sync(0xFFFFFFFFu, state, bb);               \
        const float iA = fmaf(bAv, fmaf(aAv, cA.x, cA.y),                    \
                              fmaf(aAv, cA.z, cA.w));                        \
        const float iB = fmaf(bBv, fmaf(aBv, cB.x, cB.y),                    \
                              fmaf(aBv, cB.z, cB.w));                        \
        state = fmaf(iB, fmaf(iA, cF.x, cF.y), fmaf(iA, cF.z, cF.w));        \
        cA = pA; cB = pB; cF = pF;                                           \
    } while (0)

    // Segment schedule (iter k loads rows 2k+2, 2k+3):
    //   iters 0..2   need rows <=7    (bar 1, already passed)
    //   iters 3..12  need rows <=27   (bar 2)
    //   ...each next bar releases 20 more rows...
    //   iters 63..64 need rows <=131  (bar 8)
#pragma unroll
    for (int i = 0; i < 3; ++i) SCAN_ITER();
#pragma unroll
    for (int seg = 0; seg < 6; ++seg) {
        b = 2 + seg;
        BAR_WAIT(b);
#pragma unroll
        for (int i = 0; i < 10; ++i) SCAN_ITER();
    }
    b = 8;
    BAR_WAIT(b);
    SCAN_ITER();
    SCAN_ITER();

    // Outputs: final[0,1] -> flat 1, final[1,2] -> flat 5, final[7,2] -> flat 23.
    if (lane == 1)  out[0] = state;
    if (lane == 5)  out[1] = state;
    if (lane == 23) out[2] = state;
}

extern "C" void kernel_launch(void* const* d_in, const int* in_sizes, int n_in,
                              void* d_out, int out_size) {
    (void)in_sizes; (void)n_in; (void)out_size;
    const float*  x  = (const float*)d_in[0];      // [2]
    const float*  w  = (const float*)d_in[1];      // [9,3,4]
    const float4* nz = (const float4*)d_in[2];     // [130,9,3,4] as float4
    float* out = (float*)d_out;                    // [3]

    const size_t smem = (size_t)UROWS * ROWS * sizeof(float4);   // 67584 B
    cudaFuncSetAttribute(one_layer_net_kernel,
                         cudaFuncAttributeMaxDynamicSharedMemorySize, (int)smem);
    one_layer_net_kernel<<<1, 256, smem>>>(x, w, nz, out);
}